// round 1
// baseline (speedup 1.0000x reference)
#include <cuda_runtime.h>
#include <math.h>

#define NRES 768
#define DN   256
#define DE   128
#define EF   30
#define JTILE 64

// ---- output layout (floats), concatenation of the reference tuple ----
#define NODE_OFF 0ULL
#define EDGE_OFF (768ULL * 256ULL)                       // 196608
#define IDX_OFF  (EDGE_OFF + 768ULL * 768ULL * 128ULL)   // 75694080
#define MI_OFF   (IDX_OFF + 768ULL * 768ULL)             // 76283904
#define MIJ_OFF  (MI_OFF + 768ULL)                       // 76284672

// scratch: per-residue frames R (row-major 3x3)
__device__ float g_R[NRES * 9];

__device__ __forceinline__ float3 ld3(const float* p) { return make_float3(p[0], p[1], p[2]); }
__device__ __forceinline__ float3 vsub(float3 a, float3 b) { return make_float3(a.x - b.x, a.y - b.y, a.z - b.z); }
__device__ __forceinline__ float  vdot(float3 a, float3 b) { return a.x * b.x + a.y * b.y + a.z * b.z; }
__device__ __forceinline__ float3 vcross(float3 a, float3 b) {
    return make_float3(a.y * b.z - a.z * b.y, a.z * b.x - a.x * b.z, a.x * b.y - a.y * b.x);
}
__device__ __forceinline__ float  vnorm(float3 a) { return sqrtf(vdot(a, a) + 1e-8f); }
__device__ __forceinline__ float3 vunit(float3 a) { float r = 1.0f / vnorm(a); return make_float3(a.x * r, a.y * r, a.z * r); }

// ============================================================================
// Node kernel: one block per residue. Thread 0 computes geometry + frame,
// all 256 threads do the 7->256 matvec.
// ============================================================================
__global__ void __launch_bounds__(256) node_kernel(
    const float* __restrict__ X, const int* __restrict__ C,
    const float* __restrict__ aux, const float* __restrict__ Wn,
    const float* __restrict__ bn, float* __restrict__ out)
{
    __shared__ float sfeat[7];
    __shared__ float smask;
    const int n = blockIdx.x;

    if (threadIdx.x == 0) {
        const float* xp = X + n * 12;
        float3 Na = ld3(xp), Ca = ld3(xp + 3), Cc = ld3(xp + 6), Ox = ld3(xp + 9);

        float d1 = logf(vnorm(vsub(Ca, Na)) + 0.001f);
        float d2 = logf(vnorm(vsub(Cc, Ca)) + 0.001f);
        float d3 = logf(vnorm(vsub(Ox, Cc)) + 0.001f);
        float a1 = vdot(vunit(vsub(Na, Ca)), vunit(vsub(Cc, Ca)));
        float a2 = vdot(vunit(vsub(Ca, Cc)), vunit(vsub(Ox, Cc)));

        float3 b0 = vsub(Ca, Na), b1 = vsub(Cc, Ca), b2 = vsub(Ox, Cc);
        float3 n1 = vcross(b0, b1), n2 = vcross(b1, b2);
        float3 ub1 = vunit(b1);
        float3 m1 = vcross(n1, ub1);
        float xx = vdot(n1, n2), yy = vdot(m1, n2);
        float r = sqrtf(xx * xx + yy * yy + 1e-8f);

        sfeat[0] = d1; sfeat[1] = d2; sfeat[2] = d3;
        sfeat[3] = a1; sfeat[4] = a2;
        sfeat[5] = yy / r; sfeat[6] = xx / r;

        float mi = (C[n] > 0) ? 1.0f : 0.0f;
        smask = mi;
        out[MI_OFF + n] = mi;

        // frames: e1 = unit(Cc-Ca), e2 = unit(v - (v.e1)e1), e3 = e1 x e2
        float3 e1 = ub1;
        float3 v  = vunit(vsub(Na, Ca));
        float d  = vdot(v, e1);
        float3 w = make_float3(v.x - d * e1.x, v.y - d * e1.y, v.z - d * e1.z);
        float3 e2 = vunit(w);
        float3 e3 = vcross(e1, e2);
        float* rp = g_R + n * 9;
        rp[0] = e1.x; rp[1] = e1.y; rp[2] = e1.z;
        rp[3] = e2.x; rp[4] = e2.y; rp[5] = e2.z;
        rp[6] = e3.x; rp[7] = e3.y; rp[8] = e3.z;
    }
    __syncthreads();

    const int c = threadIdx.x;
    float acc = bn[c];
#pragma unroll
    for (int k = 0; k < 7; k++) acc = fmaf(sfeat[k], Wn[k * DN + c], acc);
    float mi = smask;
    out[NODE_OFF + (size_t)n * DN + c] = mi * (acc + aux[(size_t)n * DN + c]);
}

// ============================================================================
// Edge kernel: block = (i, tile of 64 j). Phase 1: 64 threads compute the 30
// edge features into shared. Phase 2: 256 threads, 4 edges x 8 channels per
// thread, register-tiled matvec + aux + mask, coalesced f4 stores.
// ============================================================================
__global__ void __launch_bounds__(256) edge_kernel(
    const float* __restrict__ X, const int* __restrict__ C,
    const float* __restrict__ aux, const float* __restrict__ We,
    const float* __restrict__ be, float* __restrict__ out)
{
    __shared__ __align__(16) float sW[EF][DE];      // 15360 B
    __shared__ float sb[DE];
    __shared__ float sfeat[JTILE][32];               // 8192 B (padded 30->32)
    __shared__ float sXi[12];
    __shared__ float sRi[9];
    __shared__ float sMi;

    const int i = blockIdx.y;
    const int jbase = blockIdx.x * JTILE;
    const int tid = threadIdx.x;

    // stage weights + i-side data
    for (int t = tid; t < EF * DE; t += 256) (&sW[0][0])[t] = We[t];
    if (tid < DE) sb[tid] = be[tid];
    if (tid >= 128 && tid < 140) sXi[tid - 128] = X[i * 12 + (tid - 128)];
    if (tid >= 144 && tid < 153) sRi[tid - 144] = g_R[i * 9 + (tid - 144)];
    if (tid == 160) sMi = (C[i] > 0) ? 1.0f : 0.0f;
    __syncthreads();

    // ---- phase 1: features for 64 edges ----
    if (tid < JTILE) {
        const int e = tid;
        const int j = jbase + e;
        float xj[12];
#pragma unroll
        for (int t = 0; t < 12; t++) xj[t] = X[j * 12 + t];
        float rj[9];
#pragma unroll
        for (int t = 0; t < 9; t++) rj[t] = g_R[j * 9 + t];

        float f[EF];
        // D: 16 log-distances, [p][q] = X[i,p] - X[j,q]
#pragma unroll
        for (int p = 0; p < 4; p++) {
#pragma unroll
            for (int q = 0; q < 4; q++) {
                float dx = sXi[3 * p + 0] - xj[3 * q + 0];
                float dy = sXi[3 * p + 1] - xj[3 * q + 1];
                float dz = sXi[3 * p + 2] - xj[3 * q + 2];
                float d2 = dx * dx + dy * dy + dz * dz;
                f[p * 4 + q] = logf(sqrtf(d2 + 1e-8f) + 0.01f);
            }
        }
        // Rrel: R_i @ R_j^T  (row p of R_i dot row q of R_j)
#pragma unroll
        for (int p = 0; p < 3; p++)
#pragma unroll
            for (int q = 0; q < 3; q++)
                f[16 + p * 3 + q] = sRi[3 * p + 0] * rj[3 * q + 0]
                                  + sRi[3 * p + 1] * rj[3 * q + 1]
                                  + sRi[3 * p + 2] * rj[3 * q + 2];
        // trel = R_i @ (Ca_j - Ca_i), then unit
        float dtx = xj[3] - sXi[3], dty = xj[4] - sXi[4], dtz = xj[5] - sXi[5];
        float t0 = sRi[0] * dtx + sRi[1] * dty + sRi[2] * dtz;
        float t1 = sRi[3] * dtx + sRi[4] * dty + sRi[5] * dtz;
        float t2 = sRi[6] * dtx + sRi[7] * dty + sRi[8] * dtz;
        float rn = 1.0f / sqrtf(t0 * t0 + t1 * t1 + t2 * t2 + 1e-8f);
        f[25] = t0 * rn; f[26] = t1 * rn; f[27] = t2 * rn;
        f[28] = (C[i] == C[j]) ? 1.0f : 0.0f;
        int dsep = j - i; dsep = min(32, max(-32, dsep));
        f[29] = (float)dsep * (1.0f / 32.0f);

#pragma unroll
        for (int k = 0; k < EF; k++) sfeat[e][k] = f[k];

        // side outputs
        float mj = (C[j] > 0) ? 1.0f : 0.0f;
        out[IDX_OFF + (size_t)i * NRES + j] = (float)j;
        out[MIJ_OFF + (size_t)i * NRES + j] = sMi * mj;
    }
    __syncthreads();

    // ---- phase 2: 4 edges x 8 channels per thread ----
    const int tc = tid & 15;   // channel group (16 groups of 8 = 128)
    const int te = tid >> 4;   // edge group  (16 groups of 4 = 64)
    const int c0 = tc * 8;
    const int e0 = te * 4;

    float acc[4][8];
#pragma unroll
    for (int e = 0; e < 4; e++)
#pragma unroll
        for (int c = 0; c < 8; c++) acc[e][c] = sb[c0 + c];

#pragma unroll
    for (int k = 0; k < EF; k++) {
        float4 w0 = *(const float4*)&sW[k][c0];
        float4 w1 = *(const float4*)&sW[k][c0 + 4];
#pragma unroll
        for (int e = 0; e < 4; e++) {
            float fv = sfeat[e0 + e][k];
            acc[e][0] = fmaf(fv, w0.x, acc[e][0]);
            acc[e][1] = fmaf(fv, w0.y, acc[e][1]);
            acc[e][2] = fmaf(fv, w0.z, acc[e][2]);
            acc[e][3] = fmaf(fv, w0.w, acc[e][3]);
            acc[e][4] = fmaf(fv, w1.x, acc[e][4]);
            acc[e][5] = fmaf(fv, w1.y, acc[e][5]);
            acc[e][6] = fmaf(fv, w1.z, acc[e][6]);
            acc[e][7] = fmaf(fv, w1.w, acc[e][7]);
        }
    }

    const float mi = sMi;
#pragma unroll
    for (int e = 0; e < 4; e++) {
        const int j = jbase + e0 + e;
        float mij = mi * ((C[j] > 0) ? 1.0f : 0.0f);
        size_t base = ((size_t)i * NRES + j) * DE + c0;
        float4 a0 = *(const float4*)&aux[base];
        float4 a1 = *(const float4*)&aux[base + 4];
        float4 o0 = make_float4(mij * (acc[e][0] + a0.x), mij * (acc[e][1] + a0.y),
                                mij * (acc[e][2] + a0.z), mij * (acc[e][3] + a0.w));
        float4 o1 = make_float4(mij * (acc[e][4] + a1.x), mij * (acc[e][5] + a1.y),
                                mij * (acc[e][6] + a1.z), mij * (acc[e][7] + a1.w));
        *(float4*)&out[EDGE_OFF + base]     = o0;
        *(float4*)&out[EDGE_OFF + base + 4] = o1;
    }
}

extern "C" void kernel_launch(void* const* d_in, const int* in_sizes, int n_in,
                              void* d_out, int out_size)
{
    const float* X        = (const float*)d_in[0];
    const int*   C        = (const int*)  d_in[1];
    const float* node_aux = (const float*)d_in[2];
    const float* edge_aux = (const float*)d_in[3];
    const float* W_node   = (const float*)d_in[4];
    const float* b_node   = (const float*)d_in[5];
    const float* W_edge   = (const float*)d_in[6];
    const float* b_edge   = (const float*)d_in[7];
    float* out = (float*)d_out;

    node_kernel<<<NRES, 256>>>(X, C, node_aux, W_node, b_node, out);
    edge_kernel<<<dim3(NRES / JTILE, NRES), 256>>>(X, C, edge_aux, W_edge, b_edge, out);
}

// round 2
// speedup vs baseline: 1.3292x; 1.3292x over previous
#include <cuda_runtime.h>
#include <math.h>

#define NRES 768
#define DN   256
#define DE   128
#define EF   30
#define JTILE 64
#define TILES 4            // j-tiles per block
typedef unsigned long long ull;

// ---- output layout (floats), concatenation of the reference tuple ----
#define NODE_OFF 0ULL
#define EDGE_OFF (768ULL * 256ULL)                       // 196608
#define IDX_OFF  (EDGE_OFF + 768ULL * 768ULL * 128ULL)   // 75694080
#define MI_OFF   (IDX_OFF + 768ULL * 768ULL)             // 76283904
#define MIJ_OFF  (MI_OFF + 768ULL)                       // 76284672

// scratch: per-residue frames R (row-major 3x3)
__device__ float g_R[NRES * 9];

__device__ __forceinline__ float3 ld3(const float* p) { return make_float3(p[0], p[1], p[2]); }
__device__ __forceinline__ float3 vsub(float3 a, float3 b) { return make_float3(a.x - b.x, a.y - b.y, a.z - b.z); }
__device__ __forceinline__ float  vdot(float3 a, float3 b) { return a.x * b.x + a.y * b.y + a.z * b.z; }
__device__ __forceinline__ float3 vcross(float3 a, float3 b) {
    return make_float3(a.y * b.z - a.z * b.y, a.z * b.x - a.x * b.z, a.x * b.y - a.y * b.x);
}
__device__ __forceinline__ float  vnorm(float3 a) { return sqrtf(vdot(a, a) + 1e-8f); }
__device__ __forceinline__ float3 vunit(float3 a) { float r = 1.0f / vnorm(a); return make_float3(a.x * r, a.y * r, a.z * r); }

// ---- packed f32x2 helpers (sm_103a) ----
__device__ __forceinline__ ull pack2(float lo, float hi) {
    ull r; asm("mov.b64 %0, {%1, %2};" : "=l"(r) : "f"(lo), "f"(hi)); return r;
}
#define FMA2(d, a, b, c) asm("fma.rn.f32x2 %0, %1, %2, %3;" : "=l"(d) : "l"(a), "l"(b), "l"(c))
#define ADD2(d, a, b)    asm("add.rn.f32x2 %0, %1, %2;"     : "=l"(d) : "l"(a), "l"(b))
#define MUL2(d, a, b)    asm("mul.rn.f32x2 %0, %1, %2;"     : "=l"(d) : "l"(a), "l"(b))

// ============================================================================
// Node kernel
// ============================================================================
__global__ void __launch_bounds__(256) node_kernel(
    const float* __restrict__ X, const int* __restrict__ C,
    const float* __restrict__ aux, const float* __restrict__ Wn,
    const float* __restrict__ bn, float* __restrict__ out)
{
    __shared__ float sfeat[7];
    __shared__ float smask;
    const int n = blockIdx.x;

    if (threadIdx.x == 0) {
        const float* xp = X + n * 12;
        float3 Na = ld3(xp), Ca = ld3(xp + 3), Cc = ld3(xp + 6), Ox = ld3(xp + 9);

        float d1 = logf(vnorm(vsub(Ca, Na)) + 0.001f);
        float d2 = logf(vnorm(vsub(Cc, Ca)) + 0.001f);
        float d3 = logf(vnorm(vsub(Ox, Cc)) + 0.001f);
        float a1 = vdot(vunit(vsub(Na, Ca)), vunit(vsub(Cc, Ca)));
        float a2 = vdot(vunit(vsub(Ca, Cc)), vunit(vsub(Ox, Cc)));

        float3 b0 = vsub(Ca, Na), b1 = vsub(Cc, Ca), b2 = vsub(Ox, Cc);
        float3 n1 = vcross(b0, b1), n2 = vcross(b1, b2);
        float3 ub1 = vunit(b1);
        float3 m1 = vcross(n1, ub1);
        float xx = vdot(n1, n2), yy = vdot(m1, n2);
        float r = sqrtf(xx * xx + yy * yy + 1e-8f);

        sfeat[0] = d1; sfeat[1] = d2; sfeat[2] = d3;
        sfeat[3] = a1; sfeat[4] = a2;
        sfeat[5] = yy / r; sfeat[6] = xx / r;

        float mi = (C[n] > 0) ? 1.0f : 0.0f;
        smask = mi;
        out[MI_OFF + n] = mi;

        float3 e1 = ub1;
        float3 v  = vunit(vsub(Na, Ca));
        float d  = vdot(v, e1);
        float3 w = make_float3(v.x - d * e1.x, v.y - d * e1.y, v.z - d * e1.z);
        float3 e2 = vunit(w);
        float3 e3 = vcross(e1, e2);
        float* rp = g_R + n * 9;
        rp[0] = e1.x; rp[1] = e1.y; rp[2] = e1.z;
        rp[3] = e2.x; rp[4] = e2.y; rp[5] = e2.z;
        rp[6] = e3.x; rp[7] = e3.y; rp[8] = e3.z;
    }
    __syncthreads();

    const int c = threadIdx.x;
    float acc = bn[c];
#pragma unroll
    for (int k = 0; k < 7; k++) acc = fmaf(sfeat[k], Wn[k * DN + c], acc);
    float mi = smask;
    out[NODE_OFF + (size_t)n * DN + c] = mi * (acc + aux[(size_t)n * DN + c]);
}

// ============================================================================
// Edge kernel: block = (i, group of TILES j-tiles of 64). Weights staged once.
// Phase 1 (64 threads): 30 features -> transposed shared tile + mij row.
// Phase 2 (256 threads): 4 edges x 8 channels per thread, packed f32x2 FMA.
// ============================================================================
__global__ void __launch_bounds__(256, 2) edge_kernel(
    const float* __restrict__ X, const int* __restrict__ C,
    const float* __restrict__ aux, const float* __restrict__ We,
    const float* __restrict__ be, float* __restrict__ out)
{
    __shared__ __align__(16) float sW[EF][DE];            // 15360 B
    __shared__ __align__(16) float sb[DE];
    __shared__ __align__(16) float sfeatT[EF + 1][JTILE]; // row EF = mij
    __shared__ float sXi[12];
    __shared__ float sRi[9];
    __shared__ float sMi;
    __shared__ int   sCi;

    const int i = blockIdx.y;
    const int tid = threadIdx.x;

    // ---- one-time staging ----
    for (int t = tid; t < EF * DE; t += 256) (&sW[0][0])[t] = We[t];
    if (tid < DE) sb[tid] = be[tid];
    if (tid >= 128 && tid < 140) sXi[tid - 128] = X[i * 12 + (tid - 128)];
    if (tid >= 144 && tid < 153) sRi[tid - 144] = g_R[i * 9 + (tid - 144)];
    if (tid == 160) { int ci = C[i]; sCi = ci; sMi = (ci > 0) ? 1.0f : 0.0f; }
    __syncthreads();

    const int tc = tid & 15;   // channel group (16 x 8 = 128)
    const int te = tid >> 4;   // edge group  (16 x 4 = 64)
    const int c0 = tc * 8;
    const int e0 = te * 4;

    const ull* bp = (const ull*)&sb[c0];
    const ull bb0 = bp[0], bb1 = bp[1], bb2 = bp[2], bb3 = bp[3];

    for (int t = 0; t < TILES; t++) {
        const int jbase = (blockIdx.x * TILES + t) * JTILE;

        // ---- phase 1 ----
        if (tid < JTILE) {
            const int e = tid;
            const int j = jbase + e;
            float xj[12];
#pragma unroll
            for (int q = 0; q < 12; q++) xj[q] = X[j * 12 + q];
            float rj[9];
#pragma unroll
            for (int q = 0; q < 9; q++) rj[q] = g_R[j * 9 + q];

            float f[EF];
#pragma unroll
            for (int p = 0; p < 4; p++) {
#pragma unroll
                for (int q = 0; q < 4; q++) {
                    float dx = sXi[3 * p + 0] - xj[3 * q + 0];
                    float dy = sXi[3 * p + 1] - xj[3 * q + 1];
                    float dz = sXi[3 * p + 2] - xj[3 * q + 2];
                    float d2 = dx * dx + dy * dy + dz * dz;
                    f[p * 4 + q] = logf(sqrtf(d2 + 1e-8f) + 0.01f);
                }
            }
#pragma unroll
            for (int p = 0; p < 3; p++)
#pragma unroll
                for (int q = 0; q < 3; q++)
                    f[16 + p * 3 + q] = sRi[3 * p + 0] * rj[3 * q + 0]
                                      + sRi[3 * p + 1] * rj[3 * q + 1]
                                      + sRi[3 * p + 2] * rj[3 * q + 2];
            float dtx = xj[3] - sXi[3], dty = xj[4] - sXi[4], dtz = xj[5] - sXi[5];
            float t0 = sRi[0] * dtx + sRi[1] * dty + sRi[2] * dtz;
            float t1 = sRi[3] * dtx + sRi[4] * dty + sRi[5] * dtz;
            float t2 = sRi[6] * dtx + sRi[7] * dty + sRi[8] * dtz;
            float rn = 1.0f / sqrtf(t0 * t0 + t1 * t1 + t2 * t2 + 1e-8f);
            f[25] = t0 * rn; f[26] = t1 * rn; f[27] = t2 * rn;
            int cj = C[j];
            f[28] = (sCi == cj) ? 1.0f : 0.0f;
            int dsep = j - i; dsep = min(32, max(-32, dsep));
            f[29] = (float)dsep * (1.0f / 32.0f);

#pragma unroll
            for (int k = 0; k < EF; k++) sfeatT[k][e] = f[k];

            float mij = sMi * ((cj > 0) ? 1.0f : 0.0f);
            sfeatT[EF][e] = mij;
            out[IDX_OFF + (size_t)i * NRES + j] = (float)j;
            out[MIJ_OFF + (size_t)i * NRES + j] = mij;
        }
        __syncthreads();

        // ---- phase 2: packed f32x2 matvec ----
        ull a00 = bb0, a01 = bb1, a02 = bb2, a03 = bb3;
        ull a10 = bb0, a11 = bb1, a12 = bb2, a13 = bb3;
        ull a20 = bb0, a21 = bb1, a22 = bb2, a23 = bb3;
        ull a30 = bb0, a31 = bb1, a32 = bb2, a33 = bb3;

#pragma unroll
        for (int k = 0; k < EF; k++) {
            float4 fv = *(const float4*)&sfeatT[k][e0];
            ull fq0 = pack2(fv.x, fv.x);
            ull fq1 = pack2(fv.y, fv.y);
            ull fq2 = pack2(fv.z, fv.z);
            ull fq3 = pack2(fv.w, fv.w);
            ulonglong2 wA = *(const ulonglong2*)&sW[k][c0];
            ulonglong2 wB = *(const ulonglong2*)&sW[k][c0 + 4];
            FMA2(a00, fq0, wA.x, a00); FMA2(a01, fq0, wA.y, a01);
            FMA2(a02, fq0, wB.x, a02); FMA2(a03, fq0, wB.y, a03);
            FMA2(a10, fq1, wA.x, a10); FMA2(a11, fq1, wA.y, a11);
            FMA2(a12, fq1, wB.x, a12); FMA2(a13, fq1, wB.y, a13);
            FMA2(a20, fq2, wA.x, a20); FMA2(a21, fq2, wA.y, a21);
            FMA2(a22, fq2, wB.x, a22); FMA2(a23, fq2, wB.y, a23);
            FMA2(a30, fq3, wA.x, a30); FMA2(a31, fq3, wA.y, a31);
            FMA2(a32, fq3, wB.x, a32); FMA2(a33, fq3, wB.y, a33);
        }

        ull acc[4][4] = {{a00, a01, a02, a03}, {a10, a11, a12, a13},
                         {a20, a21, a22, a23}, {a30, a31, a32, a33}};
#pragma unroll
        for (int e = 0; e < 4; e++) {
            const int j = jbase + e0 + e;
            float mij = sfeatT[EF][e0 + e];
            ull m2 = pack2(mij, mij);
            size_t base = ((size_t)i * NRES + j) * DE + c0;
            ulonglong2 aA = *(const ulonglong2*)&aux[base];
            ulonglong2 aB = *(const ulonglong2*)&aux[base + 4];
            ull o0, o1, o2, o3;
            ADD2(o0, acc[e][0], aA.x); MUL2(o0, o0, m2);
            ADD2(o1, acc[e][1], aA.y); MUL2(o1, o1, m2);
            ADD2(o2, acc[e][2], aB.x); MUL2(o2, o2, m2);
            ADD2(o3, acc[e][3], aB.y); MUL2(o3, o3, m2);
            ulonglong2 s0; s0.x = o0; s0.y = o1;
            ulonglong2 s1; s1.x = o2; s1.y = o3;
            *(ulonglong2*)&out[EDGE_OFF + base]     = s0;
            *(ulonglong2*)&out[EDGE_OFF + base + 4] = s1;
        }
        __syncthreads();
    }
}

extern "C" void kernel_launch(void* const* d_in, const int* in_sizes, int n_in,
                              void* d_out, int out_size)
{
    const float* X        = (const float*)d_in[0];
    const int*   C        = (const int*)  d_in[1];
    const float* node_aux = (const float*)d_in[2];
    const float* edge_aux = (const float*)d_in[3];
    const float* W_node   = (const float*)d_in[4];
    const float* b_node   = (const float*)d_in[5];
    const float* W_edge   = (const float*)d_in[6];
    const float* b_edge   = (const float*)d_in[7];
    float* out = (float*)d_out;

    node_kernel<<<NRES, 256>>>(X, C, node_aux, W_node, b_node, out);
    edge_kernel<<<dim3(NRES / (JTILE * TILES), NRES), 256>>>(
        X, C, edge_aux, W_edge, b_edge, out);
}

// round 3
// speedup vs baseline: 1.3873x; 1.0438x over previous
#include <cuda_runtime.h>
#include <math.h>

#define NRES 768
#define DN   256
#define DE   128
#define EF   30
#define KP   32            // padded K for MMA
#define JTILE 64
#define TILES 4            // j-tiles per block
typedef unsigned long long ull;

// ---- output layout (floats), concatenation of the reference tuple ----
#define NODE_OFF 0ULL
#define EDGE_OFF (768ULL * 256ULL)                       // 196608
#define IDX_OFF  (EDGE_OFF + 768ULL * 768ULL * 128ULL)   // 75694080
#define MI_OFF   (IDX_OFF + 768ULL * 768ULL)             // 76283904
#define MIJ_OFF  (MI_OFF + 768ULL)                       // 76284672

// scratch: per-residue frames R (row-major 3x3)
__device__ float g_R[NRES * 9];

__device__ __forceinline__ float3 ld3(const float* p) { return make_float3(p[0], p[1], p[2]); }
__device__ __forceinline__ float3 vsub(float3 a, float3 b) { return make_float3(a.x - b.x, a.y - b.y, a.z - b.z); }
__device__ __forceinline__ float  vdot(float3 a, float3 b) { return a.x * b.x + a.y * b.y + a.z * b.z; }
__device__ __forceinline__ float3 vcross(float3 a, float3 b) {
    return make_float3(a.y * b.z - a.z * b.y, a.z * b.x - a.x * b.z, a.x * b.y - a.y * b.x);
}
__device__ __forceinline__ float  vnorm(float3 a) { return sqrtf(vdot(a, a) + 1e-8f); }
__device__ __forceinline__ float3 vunit(float3 a) { float r = 1.0f / vnorm(a); return make_float3(a.x * r, a.y * r, a.z * r); }

// tf32 round (rna) -> fp32 bit pattern with low mantissa cleared
__device__ __forceinline__ unsigned tf32r(float x) {
    unsigned r; asm("cvt.rna.tf32.f32 %0, %1;" : "=r"(r) : "f"(x)); return r;
}

// m16n8k8 tf32 MMA, D += A*B
__device__ __forceinline__ void mma_tf32(float d[4], const unsigned a[4], const unsigned b[2]) {
    asm volatile(
        "mma.sync.aligned.m16n8k8.row.col.f32.tf32.tf32.f32 "
        "{%0,%1,%2,%3}, {%4,%5,%6,%7}, {%8,%9}, {%0,%1,%2,%3};"
        : "+f"(d[0]), "+f"(d[1]), "+f"(d[2]), "+f"(d[3])
        : "r"(a[0]), "r"(a[1]), "r"(a[2]), "r"(a[3]), "r"(b[0]), "r"(b[1]));
}

// ============================================================================
// Node kernel (unchanged; tiny)
// ============================================================================
__global__ void __launch_bounds__(256) node_kernel(
    const float* __restrict__ X, const int* __restrict__ C,
    const float* __restrict__ aux, const float* __restrict__ Wn,
    const float* __restrict__ bn, float* __restrict__ out)
{
    __shared__ float sfeat[7];
    __shared__ float smask;
    const int n = blockIdx.x;

    if (threadIdx.x == 0) {
        const float* xp = X + n * 12;
        float3 Na = ld3(xp), Ca = ld3(xp + 3), Cc = ld3(xp + 6), Ox = ld3(xp + 9);

        float d1 = logf(vnorm(vsub(Ca, Na)) + 0.001f);
        float d2 = logf(vnorm(vsub(Cc, Ca)) + 0.001f);
        float d3 = logf(vnorm(vsub(Ox, Cc)) + 0.001f);
        float a1 = vdot(vunit(vsub(Na, Ca)), vunit(vsub(Cc, Ca)));
        float a2 = vdot(vunit(vsub(Ca, Cc)), vunit(vsub(Ox, Cc)));

        float3 b0 = vsub(Ca, Na), b1 = vsub(Cc, Ca), b2 = vsub(Ox, Cc);
        float3 n1 = vcross(b0, b1), n2 = vcross(b1, b2);
        float3 ub1 = vunit(b1);
        float3 m1 = vcross(n1, ub1);
        float xx = vdot(n1, n2), yy = vdot(m1, n2);
        float r = sqrtf(xx * xx + yy * yy + 1e-8f);

        sfeat[0] = d1; sfeat[1] = d2; sfeat[2] = d3;
        sfeat[3] = a1; sfeat[4] = a2;
        sfeat[5] = yy / r; sfeat[6] = xx / r;

        float mi = (C[n] > 0) ? 1.0f : 0.0f;
        smask = mi;
        out[MI_OFF + n] = mi;

        float3 e1 = ub1;
        float3 v  = vunit(vsub(Na, Ca));
        float d  = vdot(v, e1);
        float3 w = make_float3(v.x - d * e1.x, v.y - d * e1.y, v.z - d * e1.z);
        float3 e2 = vunit(w);
        float3 e3 = vcross(e1, e2);
        float* rp = g_R + n * 9;
        rp[0] = e1.x; rp[1] = e1.y; rp[2] = e1.z;
        rp[3] = e2.x; rp[4] = e2.y; rp[5] = e2.z;
        rp[6] = e3.x; rp[7] = e3.y; rp[8] = e3.z;
    }
    __syncthreads();

    const int c = threadIdx.x;
    float acc = bn[c];
#pragma unroll
    for (int k = 0; k < 7; k++) acc = fmaf(sfeat[k], Wn[k * DN + c], acc);
    float mi = smask;
    out[NODE_OFF + (size_t)n * DN + c] = mi * (acc + aux[(size_t)n * DN + c]);
}

// ============================================================================
// Edge kernel: tensor-core (3xTF32 split) GEMM per 64x128 tile.
//   A = features [64 x 32], B = W_edge^T [128 x 32] (both hi/lo tf32 in smem).
//   8 warps, each computes a 32x32 output patch via m16n8k8 MMAs.
// Dynamic smem; weights staged (and split) once per block.
// ============================================================================
__global__ void __launch_bounds__(256, 2) edge_kernel(
    const float* __restrict__ X, const int* __restrict__ C,
    const float* __restrict__ aux, const float* __restrict__ We,
    const float* __restrict__ be, float* __restrict__ out)
{
    extern __shared__ __align__(16) unsigned char dsm[];
    unsigned* sAh = (unsigned*)dsm;            // [64][36]
    unsigned* sAl = sAh + 64 * 36;             // [64][36]
    unsigned* sBh = sAl + 64 * 36;             // [128][36]  (c-major: [c][k])
    unsigned* sBl = sBh + 128 * 36;            // [128][36]
    float*    sb   = (float*)(sBl + 128 * 36); // [128]
    float*    smij = sb + DE;                  // [64]

    __shared__ float sXi[12];
    __shared__ float sRi[9];
    __shared__ float sMi;
    __shared__ int   sCi;

    const int i   = blockIdx.y;
    const int tid = threadIdx.x;
    const int lane = tid & 31, warp = tid >> 5;
    const int gid = lane >> 2, tg = lane & 3;
    const int wm = warp & 1;       // 2 m-blocks of 32 edges
    const int wn = warp >> 1;      // 4 n-blocks of 32 channels

    // ---- one-time staging: split weights to tf32 hi/lo, transposed [c][k] ----
    for (int t = tid; t < KP * DE; t += 256) {
        int k = t >> 7, c = t & 127;
        float w = (k < EF) ? We[k * DE + c] : 0.0f;
        unsigned hi = tf32r(w);
        sBh[c * 36 + k] = hi;
        sBl[c * 36 + k] = tf32r(w - __uint_as_float(hi));
    }
    if (tid < DE) sb[tid] = be[tid];
    if (tid >= 128 && tid < 140) sXi[tid - 128] = X[i * 12 + (tid - 128)];
    if (tid >= 144 && tid < 153) sRi[tid - 144] = g_R[i * 9 + (tid - 144)];
    if (tid == 160) { int ci = C[i]; sCi = ci; sMi = (ci > 0) ? 1.0f : 0.0f; }
    __syncthreads();

    for (int t = 0; t < TILES; t++) {
        const int jbase = (blockIdx.x * TILES + t) * JTILE;

        // ---- phase 1: 64 threads compute 30 features, split to tf32 hi/lo ----
        if (tid < JTILE) {
            const int e = tid;
            const int j = jbase + e;
            float xj[12];
#pragma unroll
            for (int q = 0; q < 12; q++) xj[q] = X[j * 12 + q];
            float rj[9];
#pragma unroll
            for (int q = 0; q < 9; q++) rj[q] = g_R[j * 9 + q];

            float f[EF];
#pragma unroll
            for (int p = 0; p < 4; p++) {
#pragma unroll
                for (int q = 0; q < 4; q++) {
                    float dx = sXi[3 * p + 0] - xj[3 * q + 0];
                    float dy = sXi[3 * p + 1] - xj[3 * q + 1];
                    float dz = sXi[3 * p + 2] - xj[3 * q + 2];
                    float d2 = dx * dx + dy * dy + dz * dz;
                    f[p * 4 + q] = logf(sqrtf(d2 + 1e-8f) + 0.01f);
                }
            }
#pragma unroll
            for (int p = 0; p < 3; p++)
#pragma unroll
                for (int q = 0; q < 3; q++)
                    f[16 + p * 3 + q] = sRi[3 * p + 0] * rj[3 * q + 0]
                                      + sRi[3 * p + 1] * rj[3 * q + 1]
                                      + sRi[3 * p + 2] * rj[3 * q + 2];
            float dtx = xj[3] - sXi[3], dty = xj[4] - sXi[4], dtz = xj[5] - sXi[5];
            float t0 = sRi[0] * dtx + sRi[1] * dty + sRi[2] * dtz;
            float t1 = sRi[3] * dtx + sRi[4] * dty + sRi[5] * dtz;
            float t2 = sRi[6] * dtx + sRi[7] * dty + sRi[8] * dtz;
            float rn = 1.0f / sqrtf(t0 * t0 + t1 * t1 + t2 * t2 + 1e-8f);
            f[25] = t0 * rn; f[26] = t1 * rn; f[27] = t2 * rn;
            int cj = C[j];
            f[28] = (sCi == cj) ? 1.0f : 0.0f;
            int dsep = j - i; dsep = min(32, max(-32, dsep));
            f[29] = (float)dsep * (1.0f / 32.0f);

#pragma unroll
            for (int k = 0; k < EF; k++) {
                unsigned hi = tf32r(f[k]);
                sAh[e * 36 + k] = hi;
                sAl[e * 36 + k] = tf32r(f[k] - __uint_as_float(hi));
            }
            sAh[e * 36 + 30] = 0u; sAh[e * 36 + 31] = 0u;
            sAl[e * 36 + 30] = 0u; sAl[e * 36 + 31] = 0u;

            float mij = sMi * ((cj > 0) ? 1.0f : 0.0f);
            smij[e] = mij;
            out[IDX_OFF + (size_t)i * NRES + j] = (float)j;
            out[MIJ_OFF + (size_t)i * NRES + j] = mij;
        }
        __syncthreads();

        // ---- phase 2: 3xTF32 MMA. warp patch = 32 edges x 32 channels ----
        float acc[2][4][4] = {};
#pragma unroll
        for (int kt = 0; kt < 4; kt++) {
            const int k0 = kt * 8 + tg;
            unsigned ah[2][4], al[2][4];
#pragma unroll
            for (int m = 0; m < 2; m++) {
                const int e = wm * 32 + m * 16 + gid;
                ah[m][0] = sAh[e * 36 + k0];
                ah[m][1] = sAh[(e + 8) * 36 + k0];
                ah[m][2] = sAh[e * 36 + k0 + 4];
                ah[m][3] = sAh[(e + 8) * 36 + k0 + 4];
                al[m][0] = sAl[e * 36 + k0];
                al[m][1] = sAl[(e + 8) * 36 + k0];
                al[m][2] = sAl[e * 36 + k0 + 4];
                al[m][3] = sAl[(e + 8) * 36 + k0 + 4];
            }
            unsigned bh[4][2], bl[4][2];
#pragma unroll
            for (int n = 0; n < 4; n++) {
                const int c = wn * 32 + n * 8 + gid;
                bh[n][0] = sBh[c * 36 + k0];
                bh[n][1] = sBh[c * 36 + k0 + 4];
                bl[n][0] = sBl[c * 36 + k0];
                bl[n][1] = sBl[c * 36 + k0 + 4];
            }
#pragma unroll
            for (int m = 0; m < 2; m++)
#pragma unroll
                for (int n = 0; n < 4; n++) {
                    mma_tf32(acc[m][n], ah[m], bh[n]);
                    mma_tf32(acc[m][n], ah[m], bl[n]);
                    mma_tf32(acc[m][n], al[m], bh[n]);
                }
        }

        // ---- epilogue: + bias + aux, * mij, float2 stores ----
#pragma unroll
        for (int m = 0; m < 2; m++) {
            const int el0 = wm * 32 + m * 16 + gid;
            const int el1 = el0 + 8;
            const float mj0 = smij[el0];
            const float mj1 = smij[el1];
            const int j0 = jbase + el0, j1 = jbase + el1;
#pragma unroll
            for (int n = 0; n < 4; n++) {
                const int c = wn * 32 + n * 8 + 2 * tg;
                float2 bv = *(const float2*)&sb[c];
                size_t base0 = ((size_t)i * NRES + j0) * DE + c;
                size_t base1 = ((size_t)i * NRES + j1) * DE + c;
                float2 a0 = *(const float2*)&aux[base0];
                float2 a1 = *(const float2*)&aux[base1];
                float2 o0, o1;
                o0.x = mj0 * (acc[m][n][0] + bv.x + a0.x);
                o0.y = mj0 * (acc[m][n][1] + bv.y + a0.y);
                o1.x = mj1 * (acc[m][n][2] + bv.x + a1.x);
                o1.y = mj1 * (acc[m][n][3] + bv.y + a1.y);
                *(float2*)&out[EDGE_OFF + base0] = o0;
                *(float2*)&out[EDGE_OFF + base1] = o1;
            }
        }
        __syncthreads();   // protect sA / smij before next tile
    }
}

#define EDGE_DSM ((2 * 64 * 36 + 2 * 128 * 36) * 4 + (DE + JTILE) * 4)

extern "C" void kernel_launch(void* const* d_in, const int* in_sizes, int n_in,
                              void* d_out, int out_size)
{
    const float* X        = (const float*)d_in[0];
    const int*   C        = (const int*)  d_in[1];
    const float* node_aux = (const float*)d_in[2];
    const float* edge_aux = (const float*)d_in[3];
    const float* W_node   = (const float*)d_in[4];
    const float* b_node   = (const float*)d_in[5];
    const float* W_edge   = (const float*)d_in[6];
    const float* b_edge   = (const float*)d_in[7];
    float* out = (float*)d_out;

    cudaFuncSetAttribute(edge_kernel,
                         cudaFuncAttributeMaxDynamicSharedMemorySize, EDGE_DSM);

    node_kernel<<<NRES, 256>>>(X, C, node_aux, W_node, b_node, out);
    edge_kernel<<<dim3(NRES / (JTILE * TILES), NRES), 256, EDGE_DSM>>>(
        X, C, edge_aux, W_edge, b_edge, out);
}